// round 16
// baseline (speedup 1.0000x reference)
#include <cuda_runtime.h>
#include <cuda_bf16.h>
#include <cstdint>

#define NN 50000
#define EE 1600000
#define DD 128
#define GG 64
#define IN_F 9
#define DEG_CAP 96          // Poisson(32): P(deg>=96) ~ 1e-30 per node

typedef unsigned long long ull;

// ---------------- f32x2 packed-math helpers (PTX-only) -----------------------
__device__ __forceinline__ ull pack2(float x, float y) {
    ull r; asm("mov.b64 %0, {%1, %2};" : "=l"(r) : "f"(x), "f"(y)); return r;
}
__device__ __forceinline__ void unpack2(ull v, float& x, float& y) {
    asm("mov.b64 {%0, %1}, %2;" : "=f"(x), "=f"(y) : "l"(v));
}
__device__ __forceinline__ void ffma2(ull& d, ull a, ull b) {
    asm("fma.rn.f32x2 %0, %1, %2, %3;" : "=l"(d) : "l"(a), "l"(b), "l"(d));
}
__device__ __forceinline__ uint32_t smem_u32(const void* p) {
    uint32_t a;
    asm("{ .reg .u64 t; cvta.to.shared.u64 t, %1; cvt.u32.u64 %0, t; }"
        : "=r"(a) : "l"(p));
    return a;
}
__device__ __forceinline__ void cp_async16(uint32_t dst, const void* src) {
    asm volatile("cp.async.cg.shared.global [%0], [%1], 16;" :: "r"(dst), "l"(src));
}
__device__ __forceinline__ void cp_async4_z(uint32_t dst, const void* src, bool valid) {
    int sz = valid ? 4 : 0;
    asm volatile("cp.async.ca.shared.global [%0], [%1], 4, %2;"
                 :: "r"(dst), "l"(src), "r"(sz));
}

// ---------------- scratch: __device__ globals --------------------------------
__device__ float          d_h0[NN * DD];
__device__ float          d_h1[NN * DD];
__device__ __nv_bfloat162 d_h0b[NN * DD / 2];
__device__ __nv_bfloat162 d_h1b[NN * DD / 2];
__device__ int            d_cnt[NN];
__device__ int            d_csr[NN * DEG_CAP];
__device__ float          d_gsum[GG * DD];
__device__ unsigned       d_gmax[GG * DD];
__device__ int            d_gcnt[GG];

// ---------------- init: zero everything --------------------------------------
__global__ void init_kernel() {
    int i = blockIdx.x * blockDim.x + threadIdx.x;
    if (i < NN) d_cnt[i] = 0;
    if (i < GG * DD) { d_gsum[i] = 0.f; d_gmax[i] = 0u; }
    if (i < GG) d_gcnt[i] = 0;
}

// ---------------- CSR fill (fixed stride, no prefix sum) ---------------------
__global__ void fill_csr_kernel(const int* __restrict__ ei) {
    int e = blockIdx.x * blockDim.x + threadIdx.x;
    if (e < EE) {
        int src = ei[e];
        int dst = ei[EE + e];
        int pos = atomicAdd(&d_cnt[dst], 1);
        if (pos < DEG_CAP) d_csr[dst * DEG_CAP + pos] = src;
    }
}

// ---------------- node embedder: Linear(9->128)+LN+ReLU, 8 rows/warp ---------
__global__ void __launch_bounds__(256) embed_kernel(
    const float* __restrict__ x, const float* __restrict__ W,
    const float* __restrict__ bias, const float* __restrict__ gamma,
    const float* __restrict__ beta) {
    int tid = threadIdx.x;
    int wid = tid >> 5, lane = tid & 31;
    int c = lane * 4;

    float4 wr[IN_F];
#pragma unroll
    for (int k = 0; k < IN_F; k++) wr[k] = *(const float4*)&W[k * 128 + c];
    float4 bv = *(const float4*)&bias[c];
    float4 gv = *(const float4*)&gamma[c];
    float4 tv = *(const float4*)&beta[c];

    int base = (blockIdx.x * 8 + wid) * 8;
#pragma unroll
    for (int r = 0; r < 8; r++) {
        int row = base + r;
        if (row >= NN) return;
        float4 a = bv;
#pragma unroll
        for (int k = 0; k < IN_F; k++) {
            float xv = __ldg(&x[row * IN_F + k]);
            a.x += xv * wr[k].x; a.y += xv * wr[k].y;
            a.z += xv * wr[k].z; a.w += xv * wr[k].w;
        }
        float s = a.x + a.y + a.z + a.w;
        float q = a.x * a.x + a.y * a.y + a.z * a.z + a.w * a.w;
#pragma unroll
        for (int off = 16; off > 0; off >>= 1) {
            s += __shfl_xor_sync(0xFFFFFFFFu, s, off);
            q += __shfl_xor_sync(0xFFFFFFFFu, q, off);
        }
        float mean = s * (1.f / 128.f);
        float var = q * (1.f / 128.f) - mean * mean;
        float rstd = rsqrtf(var + 1e-5f);
        float4 o;
        o.x = fmaxf((a.x - mean) * rstd * gv.x + tv.x, 0.f);
        o.y = fmaxf((a.y - mean) * rstd * gv.y + tv.y, 0.f);
        o.z = fmaxf((a.z - mean) * rstd * gv.z + tv.z, 0.f);
        o.w = fmaxf((a.w - mean) * rstd * gv.w + tv.w, 0.f);
        *(float4*)(d_h0 + (size_t)row * DD + c) = o;
        d_h0b[(size_t)row * 64 + lane * 2]     = __float22bfloat162_rn(make_float2(o.x, o.y));
        d_h0b[(size_t)row * 64 + lane * 2 + 1] = __float22bfloat162_rn(make_float2(o.z, o.w));
    }
}

// ---------------- fused AGG + GEMM + bias + LN + ReLU ------------------------
// out[m] = relu(LN( concat(h[m], nmean[m]) @ W + b )), K = 256, nmean computed
// in-kernel: during k-chunks 0-7 (h phase), warp ty gathers row ty*8+c's
// neighbor mean (bf16 gather, f32 accum) into smem nmt[k][m]; chunks 8-15 read
// A from nmt. 3-stage cp.async pipeline, one __syncthreads per chunk.
// Dynamic smem: As 3*16*68 | Ws 3*16*128 | nmt 128*68  = 72448 B.
#define CH 16
#define SM_AS   0
#define SM_WS   3264
#define SM_NMT  9408
#define SM_FTOT 18112
template <int A1B, int OB, int OBB>
__global__ void __launch_bounds__(256, 3) gemm_fused_kernel(
    float* __restrict__ Oext,
    const float* __restrict__ W, const float* __restrict__ bias,
    const float* __restrict__ gamma, const float* __restrict__ beta) {
    extern __shared__ float smf[];
    const float* __restrict__ A1 = (A1B == 0) ? d_h0 : d_h1;
    const __nv_bfloat162* __restrict__ hbsrc = (A1B == 0) ? d_h0b : d_h1b;
    float* __restrict__ out = (OB == 0) ? d_h0 : (OB == 1) ? d_h1 : Oext;

    float* As  = smf + SM_AS;    // [(s*16+kk)*68 + m]
    float* Ws  = smf + SM_WS;    // [(s*16+kk)*128 + col]
    float* nmt = smf + SM_NMT;   // [k*68 + m]

    const int tid = threadIdx.x;
    const int tx = tid & 31;
    const int ty = tid >> 5;
    const int row0 = blockIdx.x * 64;
    const uint32_t sAs = smem_u32(As);
    const uint32_t sWs = smem_u32(Ws);

    const int wk0 = tid >> 5;
    const int wo0 = (tid & 31) * 16;
    const int wk1 = (tid + 256) >> 5;

    ull acc[4][4];
#pragma unroll
    for (int p = 0; p < 4; p++)
#pragma unroll
        for (int c = 0; c < 4; c++) acc[p][c] = 0ull;

    auto load_chunk = [&](int c, int s) {
        const float* wsrc = W + (size_t)c * CH * 128;
        cp_async16(sWs + (uint32_t)(s * CH + wk0) * 512 + wo0,
                   wsrc + wk0 * 128 + (wo0 >> 2));
        cp_async16(sWs + (uint32_t)(s * CH + wk1) * 512 + wo0,
                   wsrc + wk1 * 128 + (wo0 >> 2));
        if (c < 8) {                       // h phase: A from global
            int kbase = c * CH;
#pragma unroll
            for (int i = 0; i < 4; i++) {
                int idx = tid + i * 256;
                int m = idx >> 4, kk = idx & 15;
                int gr = row0 + m;
                int grc = (gr < NN) ? gr : 0;
                cp_async4_z(sAs + (uint32_t)((s * CH + kk) * 68 + m) * 4,
                            A1 + (size_t)grc * 128 + kbase + kk, gr < NN);
            }
        }
        asm volatile("cp.async.commit_group;" ::: "memory");
    };

    auto compute_stage = [&](int s) {
#pragma unroll
        for (int kk = 0; kk < CH; kk++) {
            ulonglong2 ap0 = *(const ulonglong2*)&As[(s * CH + kk) * 68 + ty * 8];
            ulonglong2 ap1 = *(const ulonglong2*)&As[(s * CH + kk) * 68 + ty * 8 + 4];
            float4 wv = *(const float4*)&Ws[(s * CH + kk) * 128 + tx * 4];
            ull wp0 = pack2(wv.x, wv.x);
            ull wp1 = pack2(wv.y, wv.y);
            ull wp2 = pack2(wv.z, wv.z);
            ull wp3 = pack2(wv.w, wv.w);
            ffma2(acc[0][0], ap0.x, wp0); ffma2(acc[0][1], ap0.x, wp1);
            ffma2(acc[0][2], ap0.x, wp2); ffma2(acc[0][3], ap0.x, wp3);
            ffma2(acc[1][0], ap0.y, wp0); ffma2(acc[1][1], ap0.y, wp1);
            ffma2(acc[1][2], ap0.y, wp2); ffma2(acc[1][3], ap0.y, wp3);
            ffma2(acc[2][0], ap1.x, wp0); ffma2(acc[2][1], ap1.x, wp1);
            ffma2(acc[2][2], ap1.x, wp2); ffma2(acc[2][3], ap1.x, wp3);
            ffma2(acc[3][0], ap1.y, wp0); ffma2(acc[3][1], ap1.y, wp1);
            ffma2(acc[3][2], ap1.y, wp2); ffma2(acc[3][3], ap1.y, wp3);
        }
    };

    auto compute_nmt = [&](int kb, int s) {
#pragma unroll
        for (int kk = 0; kk < CH; kk++) {
            ulonglong2 ap0 = *(const ulonglong2*)&nmt[(kb + kk) * 68 + ty * 8];
            ulonglong2 ap1 = *(const ulonglong2*)&nmt[(kb + kk) * 68 + ty * 8 + 4];
            float4 wv = *(const float4*)&Ws[(s * CH + kk) * 128 + tx * 4];
            ull wp0 = pack2(wv.x, wv.x);
            ull wp1 = pack2(wv.y, wv.y);
            ull wp2 = pack2(wv.z, wv.z);
            ull wp3 = pack2(wv.w, wv.w);
            ffma2(acc[0][0], ap0.x, wp0); ffma2(acc[0][1], ap0.x, wp1);
            ffma2(acc[0][2], ap0.x, wp2); ffma2(acc[0][3], ap0.x, wp3);
            ffma2(acc[1][0], ap0.y, wp0); ffma2(acc[1][1], ap0.y, wp1);
            ffma2(acc[1][2], ap0.y, wp2); ffma2(acc[1][3], ap0.y, wp3);
            ffma2(acc[2][0], ap1.x, wp0); ffma2(acc[2][1], ap1.x, wp1);
            ffma2(acc[2][2], ap1.x, wp2); ffma2(acc[2][3], ap1.x, wp3);
            ffma2(acc[3][0], ap1.y, wp0); ffma2(acc[3][1], ap1.y, wp1);
            ffma2(acc[3][2], ap1.y, wp2); ffma2(acc[3][3], ap1.y, wp3);
        }
    };

    // gather one row's neighbor mean: warp ty handles block row ty*8 + c
    auto gather_row = [&](int c) {
        int m = ty * 8 + c;
        int gr = row0 + m;
        float4 g = make_float4(0.f, 0.f, 0.f, 0.f);
        if (gr < NN) {
            int n = d_cnt[gr];
            int ncl = min(n, DEG_CAP);
            const int* re = d_csr + gr * DEG_CAP;
#pragma unroll 4
            for (int i = 0; i < ncl; i++) {
                int src = re[i];
                uint2 u = *reinterpret_cast<const uint2*>(hbsrc + (size_t)src * 64 + tx * 2);
                float2 f0 = __bfloat1622float2(*reinterpret_cast<__nv_bfloat162*>(&u.x));
                float2 f1 = __bfloat1622float2(*reinterpret_cast<__nv_bfloat162*>(&u.y));
                g.x += f0.x; g.y += f0.y; g.z += f1.x; g.w += f1.y;
            }
            float inv = (n > 0) ? 1.f / (float)n : 0.f;
            g.x *= inv; g.y *= inv; g.z *= inv; g.w *= inv;
        }
        int k0 = tx * 4;     // transposed store: nmt[k][m]
        nmt[(k0 + 0) * 68 + m] = g.x;
        nmt[(k0 + 1) * 68 + m] = g.y;
        nmt[(k0 + 2) * 68 + m] = g.z;
        nmt[(k0 + 3) * 68 + m] = g.w;
    };

    load_chunk(0, 0);
    load_chunk(1, 1);
#pragma unroll 1
    for (int c = 0; c < 16; c++) {
        asm volatile("cp.async.wait_group 1;" ::: "memory");
        __syncthreads();
        int nc = (c + 2 < 16) ? (c + 2) : 15;
        load_chunk(nc, (c + 2) % 3);
        if (c < 8) {
            compute_stage(c % 3);
            gather_row(c);
        } else {
            compute_nmt((c - 8) * CH, c % 3);
        }
    }

    // epilogue: bias + LN + ReLU
    float4 bv = *(const float4*)&bias[tx * 4];
    float4 gv = *(const float4*)&gamma[tx * 4];
    float4 tv = *(const float4*)&beta[tx * 4];
    __nv_bfloat162* hb = (OBB == 1) ? d_h0b : d_h1b;
#pragma unroll
    for (int p = 0; p < 4; p++) {
#pragma unroll
        for (int h = 0; h < 2; h++) {
            int gr = row0 + ty * 8 + p * 2 + h;
            float x0, x1, x2, x3, dummy;
            if (h == 0) {
                unpack2(acc[p][0], x0, dummy);
                unpack2(acc[p][1], x1, dummy);
                unpack2(acc[p][2], x2, dummy);
                unpack2(acc[p][3], x3, dummy);
            } else {
                unpack2(acc[p][0], dummy, x0);
                unpack2(acc[p][1], dummy, x1);
                unpack2(acc[p][2], dummy, x2);
                unpack2(acc[p][3], dummy, x3);
            }
            x0 += bv.x; x1 += bv.y; x2 += bv.z; x3 += bv.w;
            float s = x0 + x1 + x2 + x3;
            float q = x0 * x0 + x1 * x1 + x2 * x2 + x3 * x3;
#pragma unroll
            for (int off = 16; off > 0; off >>= 1) {
                s += __shfl_xor_sync(0xFFFFFFFFu, s, off);
                q += __shfl_xor_sync(0xFFFFFFFFu, q, off);
            }
            float mean = s * (1.f / 128.f);
            float var = q * (1.f / 128.f) - mean * mean;
            float rstd = rsqrtf(var + 1e-5f);
            float4 o;
            o.x = fmaxf((x0 - mean) * rstd * gv.x + tv.x, 0.f);
            o.y = fmaxf((x1 - mean) * rstd * gv.y + tv.y, 0.f);
            o.z = fmaxf((x2 - mean) * rstd * gv.z + tv.z, 0.f);
            o.w = fmaxf((x3 - mean) * rstd * gv.w + tv.w, 0.f);
            if (gr < NN) {
                *(float4*)(out + (size_t)gr * 128 + tx * 4) = o;
                if (OBB != 0) {
                    __nv_bfloat162 b0 = __float22bfloat162_rn(make_float2(o.x, o.y));
                    __nv_bfloat162 b1 = __float22bfloat162_rn(make_float2(o.z, o.w));
                    uint2 u;
                    u.x = *reinterpret_cast<unsigned*>(&b0);
                    u.y = *reinterpret_cast<unsigned*>(&b1);
                    *reinterpret_cast<uint2*>(hb + (size_t)gr * 64 + tx * 2) = u;
                }
            }
        }
    }
}

// ---------------- pooling accumulate (batch sorted; also counts per-graph) ---
__global__ void __launch_bounds__(128) pool_kernel(
    const float* __restrict__ ne, const int* __restrict__ batch) {
    __shared__ int sg[128];
    int col = threadIdx.x;
    int nb = blockIdx.x * 128;
    int rows = min(128, NN - nb);
    if (col < rows) sg[col] = batch[nb + col];
    __syncthreads();

    int cur = sg[0];
    float s = 0.f, mx = 0.f;
    int rc = 0;
    for (int r = 0; r < rows; r++) {
        int g = sg[r];
        if (g != cur) {
            atomicAdd(&d_gsum[cur * DD + col], s);
            atomicMax(&d_gmax[cur * DD + col], __float_as_uint(mx));
            if (col == 0) atomicAdd(&d_gcnt[cur], rc);
            s = 0.f; mx = 0.f; rc = 0; cur = g;
        }
        float v = ne[(size_t)(nb + r) * DD + col];
        s += v;
        mx = fmaxf(mx, v);
        rc++;
    }
    atomicAdd(&d_gsum[cur * DD + col], s);
    atomicMax(&d_gmax[cur * DD + col], __float_as_uint(mx));
    if (col == 0) atomicAdd(&d_gcnt[cur], rc);
}

// ---------------- finalize graph embedding -----------------------------------
__global__ void finalize_kernel(float* __restrict__ gout) {
    int g = blockIdx.x;
    int col = threadIdx.x;
    float cnt = fmaxf((float)d_gcnt[g], 1.f);
    gout[g * 2 * DD + col] = d_gsum[g * DD + col] / cnt;
    gout[g * 2 * DD + DD + col] = __uint_as_float(d_gmax[g * DD + col]);
}

// ---------------- launch ------------------------------------------------------
extern "C" void kernel_launch(void* const* d_in, const int* in_sizes, int n_in,
                              void* d_out, int out_size) {
    const float* x     = (const float*)d_in[0];
    const int*   ei    = (const int*)d_in[1];
    const int*   batch = (const int*)d_in[2];
    const float* W_emb = (const float*)d_in[3];
    const float* b_emb = (const float*)d_in[4];
    const float* g0  = (const float*)d_in[5];
    const float* bt0 = (const float*)d_in[6];
    const float* Wc1 = (const float*)d_in[7];
    const float* bc1 = (const float*)d_in[8];
    const float* g1  = (const float*)d_in[9];
    const float* bt1 = (const float*)d_in[10];
    const float* Wc2 = (const float*)d_in[11];
    const float* bc2 = (const float*)d_in[12];
    const float* g2  = (const float*)d_in[13];
    const float* bt2 = (const float*)d_in[14];
    const float* Wc3 = (const float*)d_in[15];
    const float* bc3 = (const float*)d_in[16];
    const float* g3  = (const float*)d_in[17];
    const float* bt3 = (const float*)d_in[18];

    float* node_out  = (float*)d_out;
    float* graph_out = (float*)d_out + (size_t)NN * DD;

    const int gemm_blocks = (NN + 63) / 64;     // 782
    const int smem_bytes = SM_FTOT * 4;         // 72448

    cudaFuncSetAttribute(gemm_fused_kernel<0, 1, 2>,
                         cudaFuncAttributeMaxDynamicSharedMemorySize, smem_bytes);
    cudaFuncSetAttribute(gemm_fused_kernel<1, 0, 1>,
                         cudaFuncAttributeMaxDynamicSharedMemorySize, smem_bytes);
    cudaFuncSetAttribute(gemm_fused_kernel<0, 2, 0>,
                         cudaFuncAttributeMaxDynamicSharedMemorySize, smem_bytes);

    init_kernel<<<(NN + 255) / 256, 256>>>();
    fill_csr_kernel<<<(EE + 255) / 256, 256>>>(ei);
    embed_kernel<<<(NN + 63) / 64, 256>>>(x, W_emb, b_emb, g0, bt0);

    // fused SAGE layers (layer 1 = ncu slot 4)
    gemm_fused_kernel<0, 1, 2><<<gemm_blocks, 256, smem_bytes>>>(nullptr, Wc1, bc1, g1, bt1);
    gemm_fused_kernel<1, 0, 1><<<gemm_blocks, 256, smem_bytes>>>(nullptr, Wc2, bc2, g2, bt2);
    gemm_fused_kernel<0, 2, 0><<<gemm_blocks, 256, smem_bytes>>>(node_out, Wc3, bc3, g3, bt3);

    // pooling (also accumulates per-graph node counts)
    pool_kernel<<<(NN + 127) / 128, 128>>>(node_out, batch);
    finalize_kernel<<<GG, DD>>>(graph_out);
}

// round 17
// speedup vs baseline: 1.2167x; 1.2167x over previous
#include <cuda_runtime.h>
#include <cuda_bf16.h>
#include <cstdint>

#define NN 50000
#define EE 1600000
#define DD 128
#define GG 64
#define IN_F 9
#define DEG_CAP 96          // Poisson(32): P(deg>=96) ~ 1e-30 per node

typedef unsigned long long ull;

// ---------------- f32x2 packed-math helpers (PTX-only) -----------------------
__device__ __forceinline__ ull pack2(float x, float y) {
    ull r; asm("mov.b64 %0, {%1, %2};" : "=l"(r) : "f"(x), "f"(y)); return r;
}
__device__ __forceinline__ void unpack2(ull v, float& x, float& y) {
    asm("mov.b64 {%0, %1}, %2;" : "=f"(x), "=f"(y) : "l"(v));
}
__device__ __forceinline__ void ffma2(ull& d, ull a, ull b) {
    asm("fma.rn.f32x2 %0, %1, %2, %3;" : "=l"(d) : "l"(a), "l"(b), "l"(d));
}
__device__ __forceinline__ uint32_t smem_u32(const void* p) {
    uint32_t a;
    asm("{ .reg .u64 t; cvta.to.shared.u64 t, %1; cvt.u32.u64 %0, t; }"
        : "=r"(a) : "l"(p));
    return a;
}
__device__ __forceinline__ void cp_async16(uint32_t dst, const void* src) {
    asm volatile("cp.async.cg.shared.global [%0], [%1], 16;" :: "r"(dst), "l"(src));
}
__device__ __forceinline__ void cp_async4_z(uint32_t dst, const void* src, bool valid) {
    int sz = valid ? 4 : 0;
    asm volatile("cp.async.ca.shared.global [%0], [%1], 4, %2;"
                 :: "r"(dst), "l"(src), "r"(sz));
}

// ---------------- scratch: __device__ globals --------------------------------
__device__ float          d_h0[NN * DD];
__device__ float          d_h1[NN * DD];
__device__ float          d_nmean[NN * DD];
__device__ __nv_bfloat162 d_h0b[NN * DD / 2];
__device__ __nv_bfloat162 d_h1b[NN * DD / 2];
__device__ int            d_cnt[NN];
__device__ int            d_csr[NN * DEG_CAP];
__device__ float          d_gsum[GG * DD];
__device__ unsigned       d_gmax[GG * DD];
__device__ int            d_gcnt[GG];

// ---------------- init: zero everything --------------------------------------
__global__ void init_kernel() {
    int i = blockIdx.x * blockDim.x + threadIdx.x;
    if (i < NN) d_cnt[i] = 0;
    if (i < GG * DD) { d_gsum[i] = 0.f; d_gmax[i] = 0u; }
    if (i < GG) d_gcnt[i] = 0;
}

// ---------------- CSR fill (fixed stride, no prefix sum) ---------------------
__global__ void fill_csr_kernel(const int* __restrict__ ei) {
    int e = blockIdx.x * blockDim.x + threadIdx.x;
    if (e < EE) {
        int src = ei[e];
        int dst = ei[EE + e];
        int pos = atomicAdd(&d_cnt[dst], 1);
        if (pos < DEG_CAP) d_csr[dst * DEG_CAP + pos] = src;
    }
}

// ---------------- node embedder: Linear(9->128)+LN+ReLU, 8 rows/warp ---------
__global__ void __launch_bounds__(256) embed_kernel(
    const float* __restrict__ x, const float* __restrict__ W,
    const float* __restrict__ bias, const float* __restrict__ gamma,
    const float* __restrict__ beta) {
    int tid = threadIdx.x;
    int wid = tid >> 5, lane = tid & 31;
    int c = lane * 4;

    float4 wr[IN_F];
#pragma unroll
    for (int k = 0; k < IN_F; k++) wr[k] = *(const float4*)&W[k * 128 + c];
    float4 bv = *(const float4*)&bias[c];
    float4 gv = *(const float4*)&gamma[c];
    float4 tv = *(const float4*)&beta[c];

    int base = (blockIdx.x * 8 + wid) * 8;
#pragma unroll
    for (int r = 0; r < 8; r++) {
        int row = base + r;
        if (row >= NN) return;
        float4 a = bv;
#pragma unroll
        for (int k = 0; k < IN_F; k++) {
            float xv = __ldg(&x[row * IN_F + k]);
            a.x += xv * wr[k].x; a.y += xv * wr[k].y;
            a.z += xv * wr[k].z; a.w += xv * wr[k].w;
        }
        float s = a.x + a.y + a.z + a.w;
        float q = a.x * a.x + a.y * a.y + a.z * a.z + a.w * a.w;
#pragma unroll
        for (int off = 16; off > 0; off >>= 1) {
            s += __shfl_xor_sync(0xFFFFFFFFu, s, off);
            q += __shfl_xor_sync(0xFFFFFFFFu, q, off);
        }
        float mean = s * (1.f / 128.f);
        float var = q * (1.f / 128.f) - mean * mean;
        float rstd = rsqrtf(var + 1e-5f);
        float4 o;
        o.x = fmaxf((a.x - mean) * rstd * gv.x + tv.x, 0.f);
        o.y = fmaxf((a.y - mean) * rstd * gv.y + tv.y, 0.f);
        o.z = fmaxf((a.z - mean) * rstd * gv.z + tv.z, 0.f);
        o.w = fmaxf((a.w - mean) * rstd * gv.w + tv.w, 0.f);
        *(float4*)(d_h0 + (size_t)row * DD + c) = o;
        d_h0b[(size_t)row * 64 + lane * 2]     = __float22bfloat162_rn(make_float2(o.x, o.y));
        d_h0b[(size_t)row * 64 + lane * 2 + 1] = __float22bfloat162_rn(make_float2(o.z, o.w));
    }
}

// ---------------- neighbor mean aggregation (1 warp per dst node) -----------
// bf16 -> f32 decode via 16-bit shifts (bf16 = truncated f32): ALU-pipe ops
// that dual-issue against the FADD stream, instead of narrow-pipe F2F cvts.
template <int SB>
__global__ void __launch_bounds__(256) aggregate_kernel() {
    const __nv_bfloat162* __restrict__ hb = (SB == 0) ? d_h0b : d_h1b;
    int warp = (blockIdx.x * blockDim.x + threadIdx.x) >> 5;
    int lane = threadIdx.x & 31;
    if (warp >= NN) return;
    int n = d_cnt[warp];
    int ncl = min(n, DEG_CAP);
    const int* row = d_csr + warp * DEG_CAP;
    float4 acc = make_float4(0.f, 0.f, 0.f, 0.f);
#pragma unroll 4
    for (int i = 0; i < ncl; i++) {
        int src = row[i];
        uint2 u = *reinterpret_cast<const uint2*>(hb + (size_t)src * 64 + lane * 2);
        acc.x += __uint_as_float(u.x << 16);
        acc.y += __uint_as_float(u.x & 0xFFFF0000u);
        acc.z += __uint_as_float(u.y << 16);
        acc.w += __uint_as_float(u.y & 0xFFFF0000u);
    }
    float inv = (n > 0) ? 1.f / (float)n : 0.f;
    acc.x *= inv; acc.y *= inv; acc.z *= inv; acc.w *= inv;
    *(float4*)(d_nmean + (size_t)warp * DD + lane * 4) = acc;
}

// ---------------- fused GEMM + bias + LN + ReLU (3-stage cp.async) -----------
// out[m][0:128] = relu(LN( concat(h[m], nmean[m]) @ W + b )), K = 256.
// 64 rows x 128 cols per block, 256 threads, 8 rows x 4 cols per thread,
// row-pair f32x2 accumulators. 16 K-chunks of 16, 3-stage cp.async pipeline,
// one __syncthreads per chunk. launch_bounds(256,3) -> 3 blocks/SM.
#define CH 16
template <int A1B, int OB, int OBB>
__global__ void __launch_bounds__(256, 3) gemm_ln_relu_kernel(
    float* __restrict__ Oext,
    const float* __restrict__ W, const float* __restrict__ bias,
    const float* __restrict__ gamma, const float* __restrict__ beta) {
    const float* __restrict__ A1 = (A1B == 0) ? d_h0 : d_h1;
    const float* __restrict__ A2 = d_nmean;
    float* __restrict__ out = (OB == 0) ? d_h0 : (OB == 1) ? d_h1 : Oext;

    __shared__ float As[3][CH][68];    // [stage][k][m]
    __shared__ float Ws[3][CH][128];   // [stage][k][col]

    const int tid = threadIdx.x;
    const int tx = tid & 31;
    const int ty = tid >> 5;
    const int row0 = blockIdx.x * 64;
    const uint32_t sAs = smem_u32(As);
    const uint32_t sWs = smem_u32(Ws);

    const int wk0 = tid >> 5;
    const int wo0 = (tid & 31) * 16;
    const int wk1 = (tid + 256) >> 5;

    ull acc[4][4];
#pragma unroll
    for (int p = 0; p < 4; p++)
#pragma unroll
        for (int c = 0; c < 4; c++) acc[p][c] = 0ull;

    auto load_chunk = [&](int c, int s) {
        const float* wsrc = W + (size_t)c * CH * 128;
        cp_async16(sWs + (uint32_t)(s * CH + wk0) * 512 + wo0,
                   wsrc + wk0 * 128 + (wo0 >> 2));
        cp_async16(sWs + (uint32_t)(s * CH + wk1) * 512 + wo0,
                   wsrc + wk1 * 128 + (wo0 >> 2));
        const float* asrc = (c < 8) ? A1 : A2;
        int kbase = (c < 8) ? c * CH : (c - 8) * CH;
#pragma unroll
        for (int i = 0; i < 4; i++) {
            int idx = tid + i * 256;
            int m = idx >> 4, kk = idx & 15;
            int gr = row0 + m;
            int grc = (gr < NN) ? gr : 0;
            cp_async4_z(sAs + (uint32_t)((s * CH + kk) * 68 + m) * 4,
                        asrc + (size_t)grc * 128 + kbase + kk, gr < NN);
        }
        asm volatile("cp.async.commit_group;" ::: "memory");
    };

    auto compute = [&](int s) {
#pragma unroll
        for (int kk = 0; kk < CH; kk++) {
            ulonglong2 ap0 = *(const ulonglong2*)&As[s][kk][ty * 8];
            ulonglong2 ap1 = *(const ulonglong2*)&As[s][kk][ty * 8 + 4];
            float4 wv = *(const float4*)&Ws[s][kk][tx * 4];
            ull wp0 = pack2(wv.x, wv.x);
            ull wp1 = pack2(wv.y, wv.y);
            ull wp2 = pack2(wv.z, wv.z);
            ull wp3 = pack2(wv.w, wv.w);
            ffma2(acc[0][0], ap0.x, wp0); ffma2(acc[0][1], ap0.x, wp1);
            ffma2(acc[0][2], ap0.x, wp2); ffma2(acc[0][3], ap0.x, wp3);
            ffma2(acc[1][0], ap0.y, wp0); ffma2(acc[1][1], ap0.y, wp1);
            ffma2(acc[1][2], ap0.y, wp2); ffma2(acc[1][3], ap0.y, wp3);
            ffma2(acc[2][0], ap1.x, wp0); ffma2(acc[2][1], ap1.x, wp1);
            ffma2(acc[2][2], ap1.x, wp2); ffma2(acc[2][3], ap1.x, wp3);
            ffma2(acc[3][0], ap1.y, wp0); ffma2(acc[3][1], ap1.y, wp1);
            ffma2(acc[3][2], ap1.y, wp2); ffma2(acc[3][3], ap1.y, wp3);
        }
    };

    load_chunk(0, 0);
    load_chunk(1, 1);
#pragma unroll 1
    for (int c = 0; c < 16; c++) {
        asm volatile("cp.async.wait_group 1;" ::: "memory");
        __syncthreads();
        int nc = (c + 2 < 16) ? (c + 2) : 15;
        load_chunk(nc, (c + 2) % 3);
        compute(c % 3);
    }

    // epilogue: bias + LN + ReLU
    float4 bv = *(const float4*)&bias[tx * 4];
    float4 gv = *(const float4*)&gamma[tx * 4];
    float4 tv = *(const float4*)&beta[tx * 4];
    __nv_bfloat162* hb = (OBB == 1) ? d_h0b : d_h1b;
#pragma unroll
    for (int p = 0; p < 4; p++) {
#pragma unroll
        for (int h = 0; h < 2; h++) {
            int gr = row0 + ty * 8 + p * 2 + h;
            float x0, x1, x2, x3, dummy;
            if (h == 0) {
                unpack2(acc[p][0], x0, dummy);
                unpack2(acc[p][1], x1, dummy);
                unpack2(acc[p][2], x2, dummy);
                unpack2(acc[p][3], x3, dummy);
            } else {
                unpack2(acc[p][0], dummy, x0);
                unpack2(acc[p][1], dummy, x1);
                unpack2(acc[p][2], dummy, x2);
                unpack2(acc[p][3], dummy, x3);
            }
            x0 += bv.x; x1 += bv.y; x2 += bv.z; x3 += bv.w;
            float s = x0 + x1 + x2 + x3;
            float q = x0 * x0 + x1 * x1 + x2 * x2 + x3 * x3;
#pragma unroll
            for (int off = 16; off > 0; off >>= 1) {
                s += __shfl_xor_sync(0xFFFFFFFFu, s, off);
                q += __shfl_xor_sync(0xFFFFFFFFu, q, off);
            }
            float mean = s * (1.f / 128.f);
            float var = q * (1.f / 128.f) - mean * mean;
            float rstd = rsqrtf(var + 1e-5f);
            float4 o;
            o.x = fmaxf((x0 - mean) * rstd * gv.x + tv.x, 0.f);
            o.y = fmaxf((x1 - mean) * rstd * gv.y + tv.y, 0.f);
            o.z = fmaxf((x2 - mean) * rstd * gv.z + tv.z, 0.f);
            o.w = fmaxf((x3 - mean) * rstd * gv.w + tv.w, 0.f);
            if (gr < NN) {
                *(float4*)(out + (size_t)gr * 128 + tx * 4) = o;
                if (OBB != 0) {
                    __nv_bfloat162 b0 = __float22bfloat162_rn(make_float2(o.x, o.y));
                    __nv_bfloat162 b1 = __float22bfloat162_rn(make_float2(o.z, o.w));
                    uint2 u;
                    u.x = *reinterpret_cast<unsigned*>(&b0);
                    u.y = *reinterpret_cast<unsigned*>(&b1);
                    *reinterpret_cast<uint2*>(hb + (size_t)gr * 64 + tx * 2) = u;
                }
            }
        }
    }
}

// ---------------- pooling accumulate (batch sorted; also counts per-graph) ---
__global__ void __launch_bounds__(128) pool_kernel(
    const float* __restrict__ ne, const int* __restrict__ batch) {
    __shared__ int sg[128];
    int col = threadIdx.x;
    int nb = blockIdx.x * 128;
    int rows = min(128, NN - nb);
    if (col < rows) sg[col] = batch[nb + col];
    __syncthreads();

    int cur = sg[0];
    float s = 0.f, mx = 0.f;
    int rc = 0;
    for (int r = 0; r < rows; r++) {
        int g = sg[r];
        if (g != cur) {
            atomicAdd(&d_gsum[cur * DD + col], s);
            atomicMax(&d_gmax[cur * DD + col], __float_as_uint(mx));
            if (col == 0) atomicAdd(&d_gcnt[cur], rc);
            s = 0.f; mx = 0.f; rc = 0; cur = g;
        }
        float v = ne[(size_t)(nb + r) * DD + col];
        s += v;
        mx = fmaxf(mx, v);
        rc++;
    }
    atomicAdd(&d_gsum[cur * DD + col], s);
    atomicMax(&d_gmax[cur * DD + col], __float_as_uint(mx));
    if (col == 0) atomicAdd(&d_gcnt[cur], rc);
}

// ---------------- finalize graph embedding -----------------------------------
__global__ void finalize_kernel(float* __restrict__ gout) {
    int g = blockIdx.x;
    int col = threadIdx.x;
    float cnt = fmaxf((float)d_gcnt[g], 1.f);
    gout[g * 2 * DD + col] = d_gsum[g * DD + col] / cnt;
    gout[g * 2 * DD + DD + col] = __uint_as_float(d_gmax[g * DD + col]);
}

// ---------------- launch ------------------------------------------------------
extern "C" void kernel_launch(void* const* d_in, const int* in_sizes, int n_in,
                              void* d_out, int out_size) {
    const float* x     = (const float*)d_in[0];
    const int*   ei    = (const int*)d_in[1];
    const int*   batch = (const int*)d_in[2];
    const float* W_emb = (const float*)d_in[3];
    const float* b_emb = (const float*)d_in[4];
    const float* g0  = (const float*)d_in[5];
    const float* bt0 = (const float*)d_in[6];
    const float* Wc1 = (const float*)d_in[7];
    const float* bc1 = (const float*)d_in[8];
    const float* g1  = (const float*)d_in[9];
    const float* bt1 = (const float*)d_in[10];
    const float* Wc2 = (const float*)d_in[11];
    const float* bc2 = (const float*)d_in[12];
    const float* g2  = (const float*)d_in[13];
    const float* bt2 = (const float*)d_in[14];
    const float* Wc3 = (const float*)d_in[15];
    const float* bc3 = (const float*)d_in[16];
    const float* g3  = (const float*)d_in[17];
    const float* bt3 = (const float*)d_in[18];

    float* node_out  = (float*)d_out;
    float* graph_out = (float*)d_out + (size_t)NN * DD;

    const int gemm_blocks = (NN + 63) / 64;     // 782
    const int agg_blocks  = (NN * 32 + 255) / 256;

    init_kernel<<<(NN + 255) / 256, 256>>>();
    fill_csr_kernel<<<(EE + 255) / 256, 256>>>(ei);
    embed_kernel<<<(NN + 63) / 64, 256>>>(x, W_emb, b_emb, g0, bt0);

    // SAGE layer 1: h0 -> h1 (+h1b)   [agg1 = ncu slot 4]
    aggregate_kernel<0><<<agg_blocks, 256>>>();
    gemm_ln_relu_kernel<0, 1, 2><<<gemm_blocks, 256>>>(nullptr, Wc1, bc1, g1, bt1);

    // SAGE layer 2: h1 -> h0 (+h0b)
    aggregate_kernel<1><<<agg_blocks, 256>>>();
    gemm_ln_relu_kernel<1, 0, 1><<<gemm_blocks, 256>>>(nullptr, Wc2, bc2, g2, bt2);

    // SAGE layer 3: h0 -> node_out
    aggregate_kernel<0><<<agg_blocks, 256>>>();
    gemm_ln_relu_kernel<0, 2, 0><<<gemm_blocks, 256>>>(node_out, Wc3, bc3, g3, bt3);

    // pooling (also accumulates per-graph node counts)
    pool_kernel<<<(NN + 127) / 128, 128>>>(node_out, batch);
    finalize_kernel<<<GG, DD>>>(graph_out);
}